// round 10
// baseline (speedup 1.0000x reference)
#include <cuda_runtime.h>
#include <cuda_bf16.h>
#include <mma.h>
#include <cstdint>

using namespace nvcuda;

// Problem constants (B=8, S=4096, D=1024, H=16 heads, head_dim=64)
#define NB 8
#define NS 4096
#define ND 1024
#define NH 16

// Scratch (static device arrays; no runtime allocation allowed)
__device__ float g_G[(size_t)NB * ND * ND];  // Gram matrices  X^T X
__device__ float g_U[(size_t)NB * ND * ND];  // U = G Wq^T
__device__ float g_P[(size_t)NB * ND * ND];  // P = blockdiag(Wv_h^T A_h)
__device__ float g_M[(size_t)NB * ND * ND];  // M = P Wo^T

// ---- fp32 -> bf16 hi/lo split, packed as 4 elements (uint2 = 4 bf16) ------
__device__ __forceinline__ void split4(float4 v, uint2& h, uint2& l) {
    __nv_bfloat162 h01 = __floats2bfloat162_rn(v.x, v.y);
    __nv_bfloat162 h23 = __floats2bfloat162_rn(v.z, v.w);
    float2 f01 = __bfloat1622float2(h01);
    float2 f23 = __bfloat1622float2(h23);
    __nv_bfloat162 l01 = __floats2bfloat162_rn(v.x - f01.x, v.y - f01.y);
    __nv_bfloat162 l23 = __floats2bfloat162_rn(v.z - f23.x, v.w - f23.y);
    h.x = *(unsigned*)&h01; h.y = *(unsigned*)&h23;
    l.x = *(unsigned*)&l01; l.y = *(unsigned*)&l23;
}

#define NLD 136   // ld for [16][128] n-wide bf16 tiles (k_xtx)
#define NLD2 264  // ld for [16][256] n-wide bf16 tiles (k_xm B)
#define KLD 24    // ld for k-major bf16 tiles (48B rows; 3r mod 8 distinct -> conflict-free LDSM)

typedef wmma::fragment<wmma::accumulator, 16, 16, 16, float> AccFrag;

// ===========================================================================
// K2/K4: C_b = A_b * Bw^T  — CTA tile 128(M) x 256(N), warp tile 64x64,
// 8 warps, kTile=16, double-buffered, bf16-split wmma. Dynamic smem.
// grid (8, 4, NB), block 256.
// smem layout per buffer (stride 36864B): Ah(6144) Al(6144) Bh(12288) Bl(12288)
// ===========================================================================
#define ABT_BUF 36864
#define ABT_SMEM (2 * ABT_BUF)   // 73728

__global__ __launch_bounds__(256) void k_abt(const float* __restrict__ A0, size_t sA,
                                             const float* __restrict__ Bw,
                                             float* __restrict__ C0, size_t sC) {
    extern __shared__ char sm[];
    const int b = blockIdx.z;
    const int bi = blockIdx.x * 128, bj = blockIdx.y * 256;
    const float* A = A0 + (size_t)b * sA;
    float* C = C0 + (size_t)b * sC;

    const int t = threadIdx.x;
    const int wid = t >> 5;
    const int m0 = (wid & 1) * 64, n0 = (wid >> 1) * 64;

    AccFrag acc[4][4];
#pragma unroll
    for (int i = 0; i < 4; i++)
#pragma unroll
        for (int j = 0; j < 4; j++) wmma::fill_fragment(acc[i][j], 0.0f);

    // stage k-chunk 0 into buffer 0
    {
        char* buf = sm;
#pragma unroll
        for (int l = 0; l < 2; l++) {   // A: 128 rows x 16 k
            int e = t + l * 256;
            int r = e >> 2, kg = (e & 3) << 2;
            uint2 h, lo;
            split4(*(const float4*)&A[(size_t)(bi + r) * ND + kg], h, lo);
            *(uint2*)(buf + 0     + r * 48 + kg * 2) = h;
            *(uint2*)(buf + 6144  + r * 48 + kg * 2) = lo;
        }
#pragma unroll
        for (int l = 0; l < 4; l++) {   // B: 256 rows x 16 k
            int e = t + l * 256;
            int r = e >> 2, kg = (e & 3) << 2;
            uint2 h, lo;
            split4(*(const float4*)&Bw[(size_t)(bj + r) * ND + kg], h, lo);
            *(uint2*)(buf + 12288 + r * 48 + kg * 2) = h;
            *(uint2*)(buf + 24576 + r * 48 + kg * 2) = lo;
        }
    }
    __syncthreads();

    const int T = ND / 16;
    for (int ti = 0; ti < T; ti++) {
        const int cur = ti & 1;
        float4 ra[2], rb[4];
        const bool more = (ti + 1 < T);
        if (more) {
            int k0 = (ti + 1) * 16;
#pragma unroll
            for (int l = 0; l < 2; l++) {
                int e = t + l * 256;
                int r = e >> 2, kg = (e & 3) << 2;
                ra[l] = *(const float4*)&A[(size_t)(bi + r) * ND + k0 + kg];
            }
#pragma unroll
            for (int l = 0; l < 4; l++) {
                int e = t + l * 256;
                int r = e >> 2, kg = (e & 3) << 2;
                rb[l] = *(const float4*)&Bw[(size_t)(bj + r) * ND + k0 + kg];
            }
        }
        {
            const __nv_bfloat16* Ah = (const __nv_bfloat16*)(sm + cur * ABT_BUF);
            const __nv_bfloat16* Al = (const __nv_bfloat16*)(sm + cur * ABT_BUF + 6144);
            const __nv_bfloat16* Bh = (const __nv_bfloat16*)(sm + cur * ABT_BUF + 12288);
            const __nv_bfloat16* Bl = (const __nv_bfloat16*)(sm + cur * ABT_BUF + 24576);
            wmma::fragment<wmma::matrix_a, 16, 16, 16, __nv_bfloat16, wmma::row_major> ah[4], al[4];
#pragma unroll
            for (int i = 0; i < 4; i++) {
                wmma::load_matrix_sync(ah[i], &Ah[(m0 + 16 * i) * KLD], KLD);
                wmma::load_matrix_sync(al[i], &Al[(m0 + 16 * i) * KLD], KLD);
            }
            // B fragments loaded per-j to bound live registers (each still
            // loaded exactly once per k-tile).
#pragma unroll
            for (int j = 0; j < 4; j++) {
                wmma::fragment<wmma::matrix_b, 16, 16, 16, __nv_bfloat16, wmma::col_major> bh, bl;
                wmma::load_matrix_sync(bh, &Bh[(n0 + 16 * j) * KLD], KLD);
                wmma::load_matrix_sync(bl, &Bl[(n0 + 16 * j) * KLD], KLD);
#pragma unroll
                for (int i = 0; i < 4; i++) {
                    wmma::mma_sync(acc[i][j], ah[i], bh, acc[i][j]);
                    wmma::mma_sync(acc[i][j], ah[i], bl, acc[i][j]);
                    wmma::mma_sync(acc[i][j], al[i], bh, acc[i][j]);
                }
            }
        }
        if (more) {
            char* buf = sm + (cur ^ 1) * ABT_BUF;
#pragma unroll
            for (int l = 0; l < 2; l++) {
                int e = t + l * 256;
                int r = e >> 2, kg = (e & 3) << 2;
                uint2 h, lo;
                split4(ra[l], h, lo);
                *(uint2*)(buf + 0    + r * 48 + kg * 2) = h;
                *(uint2*)(buf + 6144 + r * 48 + kg * 2) = lo;
            }
#pragma unroll
            for (int l = 0; l < 4; l++) {
                int e = t + l * 256;
                int r = e >> 2, kg = (e & 3) << 2;
                uint2 h, lo;
                split4(rb[l], h, lo);
                *(uint2*)(buf + 12288 + r * 48 + kg * 2) = h;
                *(uint2*)(buf + 24576 + r * 48 + kg * 2) = lo;
            }
        }
        __syncthreads();
    }

#pragma unroll
    for (int i = 0; i < 4; i++)
#pragma unroll
        for (int j = 0; j < 4; j++)
            wmma::store_matrix_sync(&C[(size_t)(bi + m0 + 16 * i) * ND + bj + n0 + 16 * j],
                                    acc[i][j], ND, wmma::mem_row_major);
}

// ===========================================================================
// K5: Y_b = X_b * M_b — CTA tile 128(M) x 256(N), warp tile 64x64, 8 warps,
// kTile=16, double-buffered, bf16-split wmma. Dynamic smem.
// grid (32, 4, NB), block 256.
// smem per buffer (stride 29184B): Ah(6144) Al(6144) Bh(8448) Bl(8448)
// ===========================================================================
#define XM_BUF 29184
#define XM_SMEM (2 * XM_BUF)   // 58368

__global__ __launch_bounds__(256) void k_xm(const float* __restrict__ X,
                                            float* __restrict__ Y) {
    extern __shared__ char sm[];
    const int b = blockIdx.z;
    const int bs = blockIdx.x * 128, bo = blockIdx.y * 256;
    const float* Xb = X + (size_t)b * NS * ND;
    const float* Mb = g_M + (size_t)b * ND * ND;
    float* Yb = Y + (size_t)b * NS * ND;

    const int t = threadIdx.x;
    const int wid = t >> 5;
    const int m0 = (wid & 1) * 64, n0 = (wid >> 1) * 64;

    AccFrag acc[4][4];
#pragma unroll
    for (int i = 0; i < 4; i++)
#pragma unroll
        for (int j = 0; j < 4; j++) wmma::fill_fragment(acc[i][j], 0.0f);

    {
        char* buf = sm;
#pragma unroll
        for (int l = 0; l < 2; l++) {   // A = X: 128 rows x 16 k, k-major
            int e = t + l * 256;
            int r = e >> 2, kg = (e & 3) << 2;
            uint2 h, lo;
            split4(*(const float4*)&Xb[(size_t)(bs + r) * ND + kg], h, lo);
            *(uint2*)(buf + 0    + r * 48 + kg * 2) = h;
            *(uint2*)(buf + 6144 + r * 48 + kg * 2) = lo;
        }
#pragma unroll
        for (int l = 0; l < 4; l++) {   // B = M: 16 rows(k) x 256 cols(n), n-wide
            int e = t + l * 256;
            int row = e >> 6, col = (e & 63) << 2;
            uint2 h, lo;
            split4(*(const float4*)&Mb[(size_t)row * ND + bo + col], h, lo);
            *(uint2*)(buf + 12288 + row * 528 + col * 2) = h;
            *(uint2*)(buf + 20736 + row * 528 + col * 2) = lo;
        }
    }
    __syncthreads();

    const int T = ND / 16;
    for (int ti = 0; ti < T; ti++) {
        const int cur = ti & 1;
        float4 ra[2], rb[4];
        const bool more = (ti + 1 < T);
        if (more) {
            int k0 = (ti + 1) * 16;
#pragma unroll
            for (int l = 0; l < 2; l++) {
                int e = t + l * 256;
                int r = e >> 2, kg = (e & 3) << 2;
                ra[l] = *(const float4*)&Xb[(size_t)(bs + r) * ND + k0 + kg];
            }
#pragma unroll
            for (int l = 0; l < 4; l++) {
                int e = t + l * 256;
                int row = e >> 6, col = (e & 63) << 2;
                rb[l] = *(const float4*)&Mb[(size_t)(k0 + row) * ND + bo + col];
            }
        }
        {
            const __nv_bfloat16* Ah = (const __nv_bfloat16*)(sm + cur * XM_BUF);
            const __nv_bfloat16* Al = (const __nv_bfloat16*)(sm + cur * XM_BUF + 6144);
            const __nv_bfloat16* Bh = (const __nv_bfloat16*)(sm + cur * XM_BUF + 12288);
            const __nv_bfloat16* Bl = (const __nv_bfloat16*)(sm + cur * XM_BUF + 20736);
            wmma::fragment<wmma::matrix_a, 16, 16, 16, __nv_bfloat16, wmma::row_major> ah[4], al[4];
#pragma unroll
            for (int i = 0; i < 4; i++) {
                wmma::load_matrix_sync(ah[i], &Ah[(m0 + 16 * i) * KLD], KLD);
                wmma::load_matrix_sync(al[i], &Al[(m0 + 16 * i) * KLD], KLD);
            }
#pragma unroll
            for (int j = 0; j < 4; j++) {
                wmma::fragment<wmma::matrix_b, 16, 16, 16, __nv_bfloat16, wmma::row_major> bh, bl;
                wmma::load_matrix_sync(bh, &Bh[n0 + 16 * j], NLD2);
                wmma::load_matrix_sync(bl, &Bl[n0 + 16 * j], NLD2);
#pragma unroll
                for (int i = 0; i < 4; i++) {
                    wmma::mma_sync(acc[i][j], ah[i], bh, acc[i][j]);
                    wmma::mma_sync(acc[i][j], ah[i], bl, acc[i][j]);
                    wmma::mma_sync(acc[i][j], al[i], bh, acc[i][j]);
                }
            }
        }
        if (more) {
            char* buf = sm + (cur ^ 1) * XM_BUF;
#pragma unroll
            for (int l = 0; l < 2; l++) {
                int e = t + l * 256;
                int r = e >> 2, kg = (e & 3) << 2;
                uint2 h, lo;
                split4(ra[l], h, lo);
                *(uint2*)(buf + 0    + r * 48 + kg * 2) = h;
                *(uint2*)(buf + 6144 + r * 48 + kg * 2) = lo;
            }
#pragma unroll
            for (int l = 0; l < 4; l++) {
                int e = t + l * 256;
                int row = e >> 6, col = (e & 63) << 2;
                uint2 h, lo;
                split4(rb[l], h, lo);
                *(uint2*)(buf + 12288 + row * 528 + col * 2) = h;
                *(uint2*)(buf + 20736 + row * 528 + col * 2) = lo;
            }
        }
        __syncthreads();
    }

#pragma unroll
    for (int i = 0; i < 4; i++)
#pragma unroll
        for (int j = 0; j < 4; j++)
            wmma::store_matrix_sync(&Yb[(size_t)(bs + m0 + 16 * i) * ND + bo + n0 + 16 * j],
                                    acc[i][j], ND, wmma::mem_row_major);
}

// ===========================================================================
// K1: G_b = X_b^T X_b  (wmma, symmetric upper-tri block pairs) — unchanged R6
// ===========================================================================
__global__ __launch_bounds__(256) void k_xtx(const float* __restrict__ X) {
    const int b = blockIdx.z;
    int p = blockIdx.x, pi = 0;
    while (p >= 8 - pi) { p -= 8 - pi; pi++; }
    const int bi = pi * 128, bj = (pi + p) * 128;
    const float* Xb = X + (size_t)b * NS * ND;

    __shared__ __nv_bfloat16 Ah[2][16][NLD], Al[2][16][NLD];
    __shared__ __nv_bfloat16 Bh[2][16][NLD], Bl[2][16][NLD];

    const int t = threadIdx.x;
    const int wid = t >> 5;
    const int m0 = (wid & 1) * 64, n0 = (wid >> 1) * 32;
    const int row0 = t >> 5;
    const int col4 = t & 31;

    AccFrag acc[4][2];
#pragma unroll
    for (int i = 0; i < 4; i++)
#pragma unroll
        for (int j = 0; j < 2; j++) wmma::fill_fragment(acc[i][j], 0.0f);

#pragma unroll
    for (int l = 0; l < 2; l++) {
        int row = row0 + l * 8;
        uint2 h, lo;
        split4(*(const float4*)&Xb[(size_t)row * ND + bi + col4 * 4], h, lo);
        *(uint2*)&Ah[0][row][col4 * 4] = h; *(uint2*)&Al[0][row][col4 * 4] = lo;
        split4(*(const float4*)&Xb[(size_t)row * ND + bj + col4 * 4], h, lo);
        *(uint2*)&Bh[0][row][col4 * 4] = h; *(uint2*)&Bl[0][row][col4 * 4] = lo;
    }
    __syncthreads();

    const int T = NS / 16;
    for (int ti = 0; ti < T; ti++) {
        const int cur = ti & 1;
        float4 ra[2], rb[2];
        const bool more = (ti + 1 < T);
        if (more) {
            int y0 = (ti + 1) * 16;
#pragma unroll
            for (int l = 0; l < 2; l++) {
                int row = row0 + l * 8;
                ra[l] = *(const float4*)&Xb[(size_t)(y0 + row) * ND + bi + col4 * 4];
                rb[l] = *(const float4*)&Xb[(size_t)(y0 + row) * ND + bj + col4 * 4];
            }
        }
        {
            wmma::fragment<wmma::matrix_a, 16, 16, 16, __nv_bfloat16, wmma::col_major> ah[4], al[4];
            wmma::fragment<wmma::matrix_b, 16, 16, 16, __nv_bfloat16, wmma::row_major> bh[2], bl[2];
#pragma unroll
            for (int i = 0; i < 4; i++) {
                wmma::load_matrix_sync(ah[i], &Ah[cur][0][m0 + 16 * i], NLD);
                wmma::load_matrix_sync(al[i], &Al[cur][0][m0 + 16 * i], NLD);
            }
#pragma unroll
            for (int j = 0; j < 2; j++) {
                wmma::load_matrix_sync(bh[j], &Bh[cur][0][n0 + 16 * j], NLD);
                wmma::load_matrix_sync(bl[j], &Bl[cur][0][n0 + 16 * j], NLD);
            }
#pragma unroll
            for (int i = 0; i < 4; i++)
#pragma unroll
                for (int j = 0; j < 2; j++) {
                    wmma::mma_sync(acc[i][j], ah[i], bh[j], acc[i][j]);
                    wmma::mma_sync(acc[i][j], ah[i], bl[j], acc[i][j]);
                    wmma::mma_sync(acc[i][j], al[i], bh[j], acc[i][j]);
                }
        }
        if (more) {
            int nxt = cur ^ 1;
#pragma unroll
            for (int l = 0; l < 2; l++) {
                int row = row0 + l * 8;
                uint2 h, lo;
                split4(ra[l], h, lo);
                *(uint2*)&Ah[nxt][row][col4 * 4] = h; *(uint2*)&Al[nxt][row][col4 * 4] = lo;
                split4(rb[l], h, lo);
                *(uint2*)&Bh[nxt][row][col4 * 4] = h; *(uint2*)&Bl[nxt][row][col4 * 4] = lo;
            }
        }
        __syncthreads();
    }

    float* Gb = g_G + (size_t)b * ND * ND;
#pragma unroll
    for (int i = 0; i < 4; i++)
#pragma unroll
        for (int j = 0; j < 2; j++) {
            int mg = bi + m0 + 16 * i, ng = bj + n0 + 16 * j;
            wmma::store_matrix_sync(&Gb[(size_t)mg * ND + ng], acc[i][j], ND, wmma::mem_row_major);
            if (bi != bj)
                wmma::store_matrix_sync(&Gb[(size_t)ng * ND + mg], acc[i][j], ND, wmma::mem_col_major);
        }
}

// ===========================================================================
// K3: per (head, batch): S = Wk_h U_h / 8 ; A = softmax_rows(S) ;
//     P_h = Wv_h^T A   (fp32 SIMT) — unchanged R6
// ===========================================================================
__global__ __launch_bounds__(256, 2) void k_head(const float* __restrict__ Wk,
                                                 const float* __restrict__ Wv) {
    const int h = blockIdx.x, b = blockIdx.y;
    const float* Ub = g_U + (size_t)b * ND * ND;
    float* Pb       = g_P + (size_t)b * ND * ND;

    __shared__ float Ks[64][64];
    __shared__ float Us[64][64];
    __shared__ float Ss[64][64];

    const int t = threadIdx.x;
    const int tk = t >> 4, tq = t & 15;

    float acc[4][4];
#pragma unroll
    for (int u = 0; u < 4; u++)
#pragma unroll
        for (int v = 0; v < 4; v++) acc[u][v] = 0.f;

    for (int i0 = 0; i0 < ND; i0 += 64) {
#pragma unroll
        for (int l = 0; l < 4; l++) {
            int e = t + l * 256;
            int k = e >> 4, ig = (e & 15) << 2;
            float4 v = *(const float4*)&Wk[(size_t)(h * 64 + k) * ND + i0 + ig];
            Ks[ig + 0][k] = v.x; Ks[ig + 1][k] = v.y;
            Ks[ig + 2][k] = v.z; Ks[ig + 3][k] = v.w;
            *(float4*)&Us[k][ig] =
                *(const float4*)&Ub[(size_t)(i0 + k) * ND + h * 64 + ig];
        }
        __syncthreads();
#pragma unroll
        for (int ii = 0; ii < 64; ii++) {
            float a[4], bb[4];
            *(float4*)a  = *(float4*)&Ks[ii][tk * 4];
            *(float4*)bb = *(float4*)&Us[ii][tq * 4];
#pragma unroll
            for (int u = 0; u < 4; u++)
#pragma unroll
                for (int v = 0; v < 4; v++) acc[u][v] += a[u] * bb[v];
        }
        __syncthreads();
    }
#pragma unroll
    for (int u = 0; u < 4; u++)
#pragma unroll
        for (int v = 0; v < 4; v++)
            Ss[tk * 4 + u][tq * 4 + v] = acc[u][v] * 0.125f;  // 1/sqrt(64)
    __syncthreads();

    if (t < 64) {
        float m = -1e30f;
#pragma unroll 4
        for (int q = 0; q < 64; q++) m = fmaxf(m, Ss[t][q]);
        float s = 0.f;
#pragma unroll 4
        for (int q = 0; q < 64; q++) { float e = __expf(Ss[t][q] - m); Ss[t][q] = e; s += e; }
        float inv = 1.0f / s;
#pragma unroll 4
        for (int q = 0; q < 64; q++) Ss[t][q] *= inv;
    }
    __syncthreads();

    for (int i0 = 0; i0 < ND; i0 += 64) {
#pragma unroll
        for (int l = 0; l < 4; l++) {
            int e = t + l * 256;
            int k = e >> 4, ig = (e & 15) << 2;
            *(float4*)&Ks[k][ig] =
                *(const float4*)&Wv[(size_t)(h * 64 + k) * ND + i0 + ig];
        }
        __syncthreads();
        float acc2[4][4];
#pragma unroll
        for (int u = 0; u < 4; u++)
#pragma unroll
            for (int v = 0; v < 4; v++) acc2[u][v] = 0.f;
#pragma unroll
        for (int k = 0; k < 64; k++) {
            float a[4], bb[4];
            *(float4*)a  = *(float4*)&Ks[k][tk * 4];
            *(float4*)bb = *(float4*)&Ss[k][tq * 4];
#pragma unroll
            for (int u = 0; u < 4; u++)
#pragma unroll
                for (int v = 0; v < 4; v++) acc2[u][v] += a[u] * bb[v];
        }
        __syncthreads();
#pragma unroll
        for (int u = 0; u < 4; u++)
#pragma unroll
            for (int v = 0; v < 4; v++)
                Pb[(size_t)(i0 + tk * 4 + u) * ND + h * 64 + tq * 4 + v] = acc2[u][v];
    }
}

// ---------------------------------------------------------------------------
extern "C" void kernel_launch(void* const* d_in, const int* in_sizes, int n_in,
                              void* d_out, int out_size) {
    const float* x  = (const float*)d_in[0];
    const float* Wq = (const float*)d_in[1];
    const float* Wk = (const float*)d_in[2];
    const float* Wv = (const float*)d_in[3];
    const float* Wo = (const float*)d_in[4];
    float* y = (float*)d_out;

    float* pG = nullptr; cudaGetSymbolAddress((void**)&pG, g_G);
    float* pU = nullptr; cudaGetSymbolAddress((void**)&pU, g_U);
    float* pP = nullptr; cudaGetSymbolAddress((void**)&pP, g_P);
    float* pM = nullptr; cudaGetSymbolAddress((void**)&pM, g_M);

    cudaFuncSetAttribute(k_abt, cudaFuncAttributeMaxDynamicSharedMemorySize, ABT_SMEM);
    cudaFuncSetAttribute(k_xm,  cudaFuncAttributeMaxDynamicSharedMemorySize, XM_SMEM);

    // 1) Gram matrices: G_b = X_b^T X_b (symmetric, 36 block pairs)
    k_xtx<<<dim3(36, 1, NB), 256>>>(x);
    // 2) U_b = G_b Wq^T
    k_abt<<<dim3(8, 4, NB), 256, ABT_SMEM>>>(pG, (size_t)ND * ND, Wq, pU, (size_t)ND * ND);
    // 3) per-head scores + softmax + P_h = Wv_h^T A_h
    k_head<<<dim3(NH, NB), 256>>>(Wk, Wv);
    // 4) M_b = P_b Wo^T
    k_abt<<<dim3(8, 4, NB), 256, ABT_SMEM>>>(pP, (size_t)ND * ND, Wo, pM, (size_t)ND * ND);
    // 5) Y_b = X_b M_b
    k_xm<<<dim3(32, 4, NB), 256, XM_SMEM>>>(x, y);
}

// round 14
// speedup vs baseline: 1.1887x; 1.1887x over previous
#include <cuda_runtime.h>
#include <cuda_bf16.h>
#include <mma.h>
#include <cstdint>

using namespace nvcuda;

// Problem constants (B=8, S=4096, D=1024, H=16 heads, head_dim=64)
#define NB 8
#define NS 4096
#define ND 1024
#define NH 16

// Scratch (static device arrays; no runtime allocation allowed)
__device__ float g_G[(size_t)NB * ND * ND];  // Gram matrices  X^T X
__device__ float g_U[(size_t)NB * ND * ND];  // U = G Wq^T
__device__ float g_P[(size_t)NB * ND * ND];  // P = blockdiag(Wv_h^T A_h)
__device__ float g_M[(size_t)NB * ND * ND];  // M = P Wo^T

// ---- fp32 -> bf16 hi/lo split, packed as 4 elements (uint2 = 4 bf16) ------
__device__ __forceinline__ void split4(float4 v, uint2& h, uint2& l) {
    __nv_bfloat162 h01 = __floats2bfloat162_rn(v.x, v.y);
    __nv_bfloat162 h23 = __floats2bfloat162_rn(v.z, v.w);
    float2 f01 = __bfloat1622float2(h01);
    float2 f23 = __bfloat1622float2(h23);
    __nv_bfloat162 l01 = __floats2bfloat162_rn(v.x - f01.x, v.y - f01.y);
    __nv_bfloat162 l23 = __floats2bfloat162_rn(v.z - f23.x, v.w - f23.y);
    h.x = *(unsigned*)&h01; h.y = *(unsigned*)&h23;
    l.x = *(unsigned*)&l01; l.y = *(unsigned*)&l23;
}

#define NLD 136   // ld for [16][128] n-wide bf16 tiles
#define KLD 24    // ld for k-major bf16 tiles (48B rows; 3r mod 8 distinct -> conflict-free LDSM)

typedef wmma::fragment<wmma::accumulator, 16, 16, 16, float> AccFrag;

// ===========================================================================
// K2/K4: C_b = A_b * Bw^T — CTA tile 128x128, 4 warps (2x2), warp tile 64x64,
// kTile=16, double-buffered, bf16-split wmma, 2 CTAs/SM.
// grid (8, 8, NB), block 128, dynamic smem.
// Per buffer (stride 24576B): Ah(6144) Al(6144) Bh(6144) Bl(6144)
// ===========================================================================
#define ABT_BUF 24576
#define ABT_SMEM (2 * ABT_BUF)   // 49152

__global__ __launch_bounds__(128, 2) void k_abt(const float* __restrict__ A0, size_t sA,
                                                const float* __restrict__ Bw,
                                                float* __restrict__ C0, size_t sC) {
    extern __shared__ char sm[];
    const int b = blockIdx.z;
    const int bi = blockIdx.x * 128, bj = blockIdx.y * 128;
    const float* A = A0 + (size_t)b * sA;
    float* C = C0 + (size_t)b * sC;

    const int t = threadIdx.x;
    const int wid = t >> 5;
    const int m0 = (wid & 1) * 64, n0 = (wid >> 1) * 64;

    AccFrag acc[4][4];
#pragma unroll
    for (int i = 0; i < 4; i++)
#pragma unroll
        for (int j = 0; j < 4; j++) wmma::fill_fragment(acc[i][j], 0.0f);

    // stage k-chunk 0 into buffer 0 (each operand: 128 rows x 16 k = 512 float4)
    {
        char* buf = sm;
#pragma unroll
        for (int l = 0; l < 4; l++) {
            int e = t + l * 128;
            int r = e >> 2, kg = (e & 3) << 2;
            uint2 h, lo;
            split4(*(const float4*)&A[(size_t)(bi + r) * ND + kg], h, lo);
            *(uint2*)(buf + 0    + r * 48 + kg * 2) = h;
            *(uint2*)(buf + 6144 + r * 48 + kg * 2) = lo;
            split4(*(const float4*)&Bw[(size_t)(bj + r) * ND + kg], h, lo);
            *(uint2*)(buf + 12288 + r * 48 + kg * 2) = h;
            *(uint2*)(buf + 18432 + r * 48 + kg * 2) = lo;
        }
    }
    __syncthreads();

    const int T = ND / 16;
    for (int ti = 0; ti < T; ti++) {
        const int cur = ti & 1;
        float4 ra[4], rb[4];
        const bool more = (ti + 1 < T);
        if (more) {
            int k0 = (ti + 1) * 16;
#pragma unroll
            for (int l = 0; l < 4; l++) {
                int e = t + l * 128;
                int r = e >> 2, kg = (e & 3) << 2;
                ra[l] = *(const float4*)&A[(size_t)(bi + r) * ND + k0 + kg];
                rb[l] = *(const float4*)&Bw[(size_t)(bj + r) * ND + k0 + kg];
            }
        }
        {
            const __nv_bfloat16* Ah = (const __nv_bfloat16*)(sm + cur * ABT_BUF);
            const __nv_bfloat16* Al = (const __nv_bfloat16*)(sm + cur * ABT_BUF + 6144);
            const __nv_bfloat16* Bh = (const __nv_bfloat16*)(sm + cur * ABT_BUF + 12288);
            const __nv_bfloat16* Bl = (const __nv_bfloat16*)(sm + cur * ABT_BUF + 18432);
            wmma::fragment<wmma::matrix_a, 16, 16, 16, __nv_bfloat16, wmma::row_major> ah[4], al[4];
#pragma unroll
            for (int i = 0; i < 4; i++) {
                wmma::load_matrix_sync(ah[i], &Ah[(m0 + 16 * i) * KLD], KLD);
                wmma::load_matrix_sync(al[i], &Al[(m0 + 16 * i) * KLD], KLD);
            }
#pragma unroll
            for (int j = 0; j < 4; j++) {
                wmma::fragment<wmma::matrix_b, 16, 16, 16, __nv_bfloat16, wmma::col_major> bh, bl;
                wmma::load_matrix_sync(bh, &Bh[(n0 + 16 * j) * KLD], KLD);
                wmma::load_matrix_sync(bl, &Bl[(n0 + 16 * j) * KLD], KLD);
#pragma unroll
                for (int i = 0; i < 4; i++) {
                    wmma::mma_sync(acc[i][j], ah[i], bh, acc[i][j]);
                    wmma::mma_sync(acc[i][j], ah[i], bl, acc[i][j]);
                    wmma::mma_sync(acc[i][j], al[i], bh, acc[i][j]);
                }
            }
        }
        if (more) {
            char* buf = sm + (cur ^ 1) * ABT_BUF;
#pragma unroll
            for (int l = 0; l < 4; l++) {
                int e = t + l * 128;
                int r = e >> 2, kg = (e & 3) << 2;
                uint2 h, lo;
                split4(ra[l], h, lo);
                *(uint2*)(buf + 0    + r * 48 + kg * 2) = h;
                *(uint2*)(buf + 6144 + r * 48 + kg * 2) = lo;
                split4(rb[l], h, lo);
                *(uint2*)(buf + 12288 + r * 48 + kg * 2) = h;
                *(uint2*)(buf + 18432 + r * 48 + kg * 2) = lo;
            }
        }
        __syncthreads();
    }

#pragma unroll
    for (int i = 0; i < 4; i++)
#pragma unroll
        for (int j = 0; j < 4; j++)
            wmma::store_matrix_sync(&C[(size_t)(bi + m0 + 16 * i) * ND + bj + n0 + 16 * j],
                                    acc[i][j], ND, wmma::mem_row_major);
}

// ===========================================================================
// K5: Y_b = X_b * M_b — CTA tile 128x128, 4 warps (2x2), warp tile 64x64,
// kTile=16, double-buffered, bf16-split wmma, 2 CTAs/SM.
// grid (32, 8, NB), block 128, dynamic smem.
// Per buffer (stride 20992B): Ah(6144) Al(6144) Bh(4352) Bl(4352)
// ===========================================================================
#define XM_BUF 20992
#define XM_SMEM (2 * XM_BUF)   // 41984

__global__ __launch_bounds__(128, 2) void k_xm(const float* __restrict__ X,
                                               float* __restrict__ Y) {
    extern __shared__ char sm[];
    const int b = blockIdx.z;
    const int bs = blockIdx.x * 128, bo = blockIdx.y * 128;
    const float* Xb = X + (size_t)b * NS * ND;
    const float* Mb = g_M + (size_t)b * ND * ND;
    float* Yb = Y + (size_t)b * NS * ND;

    const int t = threadIdx.x;
    const int wid = t >> 5;
    const int m0 = (wid & 1) * 64, n0 = (wid >> 1) * 64;

    AccFrag acc[4][4];
#pragma unroll
    for (int i = 0; i < 4; i++)
#pragma unroll
        for (int j = 0; j < 4; j++) wmma::fill_fragment(acc[i][j], 0.0f);

    {
        char* buf = sm;
#pragma unroll
        for (int l = 0; l < 4; l++) {   // A = X: 128 rows x 16 k, k-major
            int e = t + l * 128;
            int r = e >> 2, kg = (e & 3) << 2;
            uint2 h, lo;
            split4(*(const float4*)&Xb[(size_t)(bs + r) * ND + kg], h, lo);
            *(uint2*)(buf + 0    + r * 48 + kg * 2) = h;
            *(uint2*)(buf + 6144 + r * 48 + kg * 2) = lo;
            // B = M: 16 rows(k) x 128 cols(n), n-wide
            int row = e >> 5, col = (e & 31) << 2;
            split4(*(const float4*)&Mb[(size_t)row * ND + bo + col], h, lo);
            *(uint2*)(buf + 12288 + row * 272 + col * 2) = h;
            *(uint2*)(buf + 16640 + row * 272 + col * 2) = lo;
        }
    }
    __syncthreads();

    const int T = ND / 16;
    for (int ti = 0; ti < T; ti++) {
        const int cur = ti & 1;
        float4 ra[4], rb[4];
        const bool more = (ti + 1 < T);
        if (more) {
            int k0 = (ti + 1) * 16;
#pragma unroll
            for (int l = 0; l < 4; l++) {
                int e = t + l * 128;
                int r = e >> 2, kg = (e & 3) << 2;
                ra[l] = *(const float4*)&Xb[(size_t)(bs + r) * ND + k0 + kg];
                int row = e >> 5, col = (e & 31) << 2;
                rb[l] = *(const float4*)&Mb[(size_t)(k0 + row) * ND + bo + col];
            }
        }
        {
            const __nv_bfloat16* Ah = (const __nv_bfloat16*)(sm + cur * XM_BUF);
            const __nv_bfloat16* Al = (const __nv_bfloat16*)(sm + cur * XM_BUF + 6144);
            const __nv_bfloat16* Bh = (const __nv_bfloat16*)(sm + cur * XM_BUF + 12288);
            const __nv_bfloat16* Bl = (const __nv_bfloat16*)(sm + cur * XM_BUF + 16640);
            wmma::fragment<wmma::matrix_a, 16, 16, 16, __nv_bfloat16, wmma::row_major> ah[4], al[4];
#pragma unroll
            for (int i = 0; i < 4; i++) {
                wmma::load_matrix_sync(ah[i], &Ah[(m0 + 16 * i) * KLD], KLD);
                wmma::load_matrix_sync(al[i], &Al[(m0 + 16 * i) * KLD], KLD);
            }
#pragma unroll
            for (int j = 0; j < 4; j++) {
                wmma::fragment<wmma::matrix_b, 16, 16, 16, __nv_bfloat16, wmma::row_major> bh, bl;
                wmma::load_matrix_sync(bh, &Bh[n0 + 16 * j], NLD);
                wmma::load_matrix_sync(bl, &Bl[n0 + 16 * j], NLD);
#pragma unroll
                for (int i = 0; i < 4; i++) {
                    wmma::mma_sync(acc[i][j], ah[i], bh, acc[i][j]);
                    wmma::mma_sync(acc[i][j], ah[i], bl, acc[i][j]);
                    wmma::mma_sync(acc[i][j], al[i], bh, acc[i][j]);
                }
            }
        }
        if (more) {
            char* buf = sm + (cur ^ 1) * XM_BUF;
#pragma unroll
            for (int l = 0; l < 4; l++) {
                int e = t + l * 128;
                int r = e >> 2, kg = (e & 3) << 2;
                uint2 h, lo;
                split4(ra[l], h, lo);
                *(uint2*)(buf + 0    + r * 48 + kg * 2) = h;
                *(uint2*)(buf + 6144 + r * 48 + kg * 2) = lo;
                int row = e >> 5, col = (e & 31) << 2;
                split4(rb[l], h, lo);
                *(uint2*)(buf + 12288 + row * 272 + col * 2) = h;
                *(uint2*)(buf + 16640 + row * 272 + col * 2) = lo;
            }
        }
        __syncthreads();
    }

#pragma unroll
    for (int i = 0; i < 4; i++)
#pragma unroll
        for (int j = 0; j < 4; j++)
            wmma::store_matrix_sync(&Yb[(size_t)(bs + m0 + 16 * i) * ND + bo + n0 + 16 * j],
                                    acc[i][j], ND, wmma::mem_row_major);
}

// ===========================================================================
// K1: G_b = X_b^T X_b  (wmma, symmetric upper-tri block pairs) — unchanged R6
// ===========================================================================
__global__ __launch_bounds__(256) void k_xtx(const float* __restrict__ X) {
    const int b = blockIdx.z;
    int p = blockIdx.x, pi = 0;
    while (p >= 8 - pi) { p -= 8 - pi; pi++; }
    const int bi = pi * 128, bj = (pi + p) * 128;
    const float* Xb = X + (size_t)b * NS * ND;

    __shared__ __nv_bfloat16 Ah[2][16][NLD], Al[2][16][NLD];
    __shared__ __nv_bfloat16 Bh[2][16][NLD], Bl[2][16][NLD];

    const int t = threadIdx.x;
    const int wid = t >> 5;
    const int m0 = (wid & 1) * 64, n0 = (wid >> 1) * 32;
    const int row0 = t >> 5;
    const int col4 = t & 31;

    AccFrag acc[4][2];
#pragma unroll
    for (int i = 0; i < 4; i++)
#pragma unroll
        for (int j = 0; j < 2; j++) wmma::fill_fragment(acc[i][j], 0.0f);

#pragma unroll
    for (int l = 0; l < 2; l++) {
        int row = row0 + l * 8;
        uint2 h, lo;
        split4(*(const float4*)&Xb[(size_t)row * ND + bi + col4 * 4], h, lo);
        *(uint2*)&Ah[0][row][col4 * 4] = h; *(uint2*)&Al[0][row][col4 * 4] = lo;
        split4(*(const float4*)&Xb[(size_t)row * ND + bj + col4 * 4], h, lo);
        *(uint2*)&Bh[0][row][col4 * 4] = h; *(uint2*)&Bl[0][row][col4 * 4] = lo;
    }
    __syncthreads();

    const int T = NS / 16;
    for (int ti = 0; ti < T; ti++) {
        const int cur = ti & 1;
        float4 ra[2], rb[2];
        const bool more = (ti + 1 < T);
        if (more) {
            int y0 = (ti + 1) * 16;
#pragma unroll
            for (int l = 0; l < 2; l++) {
                int row = row0 + l * 8;
                ra[l] = *(const float4*)&Xb[(size_t)(y0 + row) * ND + bi + col4 * 4];
                rb[l] = *(const float4*)&Xb[(size_t)(y0 + row) * ND + bj + col4 * 4];
            }
        }
        {
            wmma::fragment<wmma::matrix_a, 16, 16, 16, __nv_bfloat16, wmma::col_major> ah[4], al[4];
            wmma::fragment<wmma::matrix_b, 16, 16, 16, __nv_bfloat16, wmma::row_major> bh[2], bl[2];
#pragma unroll
            for (int i = 0; i < 4; i++) {
                wmma::load_matrix_sync(ah[i], &Ah[cur][0][m0 + 16 * i], NLD);
                wmma::load_matrix_sync(al[i], &Al[cur][0][m0 + 16 * i], NLD);
            }
#pragma unroll
            for (int j = 0; j < 2; j++) {
                wmma::load_matrix_sync(bh[j], &Bh[cur][0][n0 + 16 * j], NLD);
                wmma::load_matrix_sync(bl[j], &Bl[cur][0][n0 + 16 * j], NLD);
            }
#pragma unroll
            for (int i = 0; i < 4; i++)
#pragma unroll
                for (int j = 0; j < 2; j++) {
                    wmma::mma_sync(acc[i][j], ah[i], bh[j], acc[i][j]);
                    wmma::mma_sync(acc[i][j], ah[i], bl[j], acc[i][j]);
                    wmma::mma_sync(acc[i][j], al[i], bh[j], acc[i][j]);
                }
        }
        if (more) {
            int nxt = cur ^ 1;
#pragma unroll
            for (int l = 0; l < 2; l++) {
                int row = row0 + l * 8;
                uint2 h, lo;
                split4(ra[l], h, lo);
                *(uint2*)&Ah[nxt][row][col4 * 4] = h; *(uint2*)&Al[nxt][row][col4 * 4] = lo;
                split4(rb[l], h, lo);
                *(uint2*)&Bh[nxt][row][col4 * 4] = h; *(uint2*)&Bl[nxt][row][col4 * 4] = lo;
            }
        }
        __syncthreads();
    }

    float* Gb = g_G + (size_t)b * ND * ND;
#pragma unroll
    for (int i = 0; i < 4; i++)
#pragma unroll
        for (int j = 0; j < 2; j++) {
            int mg = bi + m0 + 16 * i, ng = bj + n0 + 16 * j;
            wmma::store_matrix_sync(&Gb[(size_t)mg * ND + ng], acc[i][j], ND, wmma::mem_row_major);
            if (bi != bj)
                wmma::store_matrix_sync(&Gb[(size_t)ng * ND + mg], acc[i][j], ND, wmma::mem_col_major);
        }
}

// ===========================================================================
// K3: per (head, batch): S = Wk_h U_h / 8 ; A = softmax_rows(S) ;
//     P_h = Wv_h^T A   (fp32 SIMT) — unchanged R6
// ===========================================================================
__global__ __launch_bounds__(256, 2) void k_head(const float* __restrict__ Wk,
                                                 const float* __restrict__ Wv) {
    const int h = blockIdx.x, b = blockIdx.y;
    const float* Ub = g_U + (size_t)b * ND * ND;
    float* Pb       = g_P + (size_t)b * ND * ND;

    __shared__ float Ks[64][64];
    __shared__ float Us[64][64];
    __shared__ float Ss[64][64];

    const int t = threadIdx.x;
    const int tk = t >> 4, tq = t & 15;

    float acc[4][4];
#pragma unroll
    for (int u = 0; u < 4; u++)
#pragma unroll
        for (int v = 0; v < 4; v++) acc[u][v] = 0.f;

    for (int i0 = 0; i0 < ND; i0 += 64) {
#pragma unroll
        for (int l = 0; l < 4; l++) {
            int e = t + l * 256;
            int k = e >> 4, ig = (e & 15) << 2;
            float4 v = *(const float4*)&Wk[(size_t)(h * 64 + k) * ND + i0 + ig];
            Ks[ig + 0][k] = v.x; Ks[ig + 1][k] = v.y;
            Ks[ig + 2][k] = v.z; Ks[ig + 3][k] = v.w;
            *(float4*)&Us[k][ig] =
                *(const float4*)&Ub[(size_t)(i0 + k) * ND + h * 64 + ig];
        }
        __syncthreads();
#pragma unroll
        for (int ii = 0; ii < 64; ii++) {
            float a[4], bb[4];
            *(float4*)a  = *(float4*)&Ks[ii][tk * 4];
            *(float4*)bb = *(float4*)&Us[ii][tq * 4];
#pragma unroll
            for (int u = 0; u < 4; u++)
#pragma unroll
                for (int v = 0; v < 4; v++) acc[u][v] += a[u] * bb[v];
        }
        __syncthreads();
    }
#pragma unroll
    for (int u = 0; u < 4; u++)
#pragma unroll
        for (int v = 0; v < 4; v++)
            Ss[tk * 4 + u][tq * 4 + v] = acc[u][v] * 0.125f;  // 1/sqrt(64)
    __syncthreads();

    if (t < 64) {
        float m = -1e30f;
#pragma unroll 4
        for (int q = 0; q < 64; q++) m = fmaxf(m, Ss[t][q]);
        float s = 0.f;
#pragma unroll 4
        for (int q = 0; q < 64; q++) { float e = __expf(Ss[t][q] - m); Ss[t][q] = e; s += e; }
        float inv = 1.0f / s;
#pragma unroll 4
        for (int q = 0; q < 64; q++) Ss[t][q] *= inv;
    }
    __syncthreads();

    for (int i0 = 0; i0 < ND; i0 += 64) {
#pragma unroll
        for (int l = 0; l < 4; l++) {
            int e = t + l * 256;
            int k = e >> 4, ig = (e & 15) << 2;
            *(float4*)&Ks[k][ig] =
                *(const float4*)&Wv[(size_t)(h * 64 + k) * ND + i0 + ig];
        }
        __syncthreads();
        float acc2[4][4];
#pragma unroll
        for (int u = 0; u < 4; u++)
#pragma unroll
            for (int v = 0; v < 4; v++) acc2[u][v] = 0.f;
#pragma unroll
        for (int k = 0; k < 64; k++) {
            float a[4], bb[4];
            *(float4*)a  = *(float4*)&Ks[k][tk * 4];
            *(float4*)bb = *(float4*)&Ss[k][tq * 4];
#pragma unroll
            for (int u = 0; u < 4; u++)
#pragma unroll
                for (int v = 0; v < 4; v++) acc2[u][v] += a[u] * bb[v];
        }
        __syncthreads();
#pragma unroll
        for (int u = 0; u < 4; u++)
#pragma unroll
            for (int v = 0; v < 4; v++)
                Pb[(size_t)(i0 + tk * 4 + u) * ND + h * 64 + tq * 4 + v] = acc2[u][v];
    }
}

// ---------------------------------------------------------------------------
extern "C" void kernel_launch(void* const* d_in, const int* in_sizes, int n_in,
                              void* d_out, int out_size) {
    const float* x  = (const float*)d_in[0];
    const float* Wq = (const float*)d_in[1];
    const float* Wk = (const float*)d_in[2];
    const float* Wv = (const float*)d_in[3];
    const float* Wo = (const float*)d_in[4];
    float* y = (float*)d_out;

    float* pG = nullptr; cudaGetSymbolAddress((void**)&pG, g_G);
    float* pU = nullptr; cudaGetSymbolAddress((void**)&pU, g_U);
    float* pP = nullptr; cudaGetSymbolAddress((void**)&pP, g_P);
    float* pM = nullptr; cudaGetSymbolAddress((void**)&pM, g_M);

    cudaFuncSetAttribute(k_abt, cudaFuncAttributeMaxDynamicSharedMemorySize, ABT_SMEM);
    cudaFuncSetAttribute(k_xm,  cudaFuncAttributeMaxDynamicSharedMemorySize, XM_SMEM);

    // 1) Gram matrices: G_b = X_b^T X_b (symmetric, 36 block pairs)
    k_xtx<<<dim3(36, 1, NB), 256>>>(x);
    // 2) U_b = G_b Wq^T
    k_abt<<<dim3(8, 8, NB), 128, ABT_SMEM>>>(pG, (size_t)ND * ND, Wq, pU, (size_t)ND * ND);
    // 3) per-head scores + softmax + P_h = Wv_h^T A_h
    k_head<<<dim3(NH, NB), 256>>>(Wk, Wv);
    // 4) M_b = P_b Wo^T
    k_abt<<<dim3(8, 8, NB), 128, ABT_SMEM>>>(pP, (size_t)ND * ND, Wo, pM, (size_t)ND * ND);
    // 5) Y_b = X_b M_b
    k_xm<<<dim3(32, 8, NB), 128, XM_SMEM>>>(x, y);
}

// round 15
// speedup vs baseline: 1.2022x; 1.0113x over previous
#include <cuda_runtime.h>
#include <cuda_bf16.h>
#include <mma.h>
#include <cstdint>

using namespace nvcuda;

// Problem constants (B=8, S=4096, D=1024, H=16 heads, head_dim=64)
#define NB 8
#define NS 4096
#define ND 1024
#define NH 16

// Scratch (static device arrays; no runtime allocation allowed)
__device__ float g_G[(size_t)NB * ND * ND];  // Gram matrices  X^T X
__device__ float g_U[(size_t)NB * ND * ND];  // U = G Wq^T
__device__ float g_P[(size_t)NB * ND * ND];  // P = blockdiag(Wv_h^T A_h)
__device__ float g_M[(size_t)NB * ND * ND];  // M = P Wo^T

// ---- fp32 -> bf16 hi/lo split, packed as 4 elements (uint2 = 4 bf16) ------
__device__ __forceinline__ void split4(float4 v, uint2& h, uint2& l) {
    __nv_bfloat162 h01 = __floats2bfloat162_rn(v.x, v.y);
    __nv_bfloat162 h23 = __floats2bfloat162_rn(v.z, v.w);
    float2 f01 = __bfloat1622float2(h01);
    float2 f23 = __bfloat1622float2(h23);
    __nv_bfloat162 l01 = __floats2bfloat162_rn(v.x - f01.x, v.y - f01.y);
    __nv_bfloat162 l23 = __floats2bfloat162_rn(v.z - f23.x, v.w - f23.y);
    h.x = *(unsigned*)&h01; h.y = *(unsigned*)&h23;
    l.x = *(unsigned*)&l01; l.y = *(unsigned*)&l23;
}

#define NLD 136   // ld for [16][128] n-wide bf16 tiles
#define KLD 24    // ld for k-major bf16 tiles (48B rows; 3r mod 8 distinct -> conflict-free LDSM)

typedef wmma::fragment<wmma::accumulator, 16, 16, 16, float> AccFrag;

// ===========================================================================
// K2/K4: C_b = A_b * Bw^T — CTA tile 128x128, 4 warps (2x2), warp tile 64x64,
// kTile=16, double-buffered, bf16-split wmma, 2 CTAs/SM. (R14 committed)
// ===========================================================================
#define ABT_BUF 24576
#define ABT_SMEM (2 * ABT_BUF)   // 49152

__global__ __launch_bounds__(128, 2) void k_abt(const float* __restrict__ A0, size_t sA,
                                                const float* __restrict__ Bw,
                                                float* __restrict__ C0, size_t sC) {
    extern __shared__ char sm[];
    const int b = blockIdx.z;
    const int bi = blockIdx.x * 128, bj = blockIdx.y * 128;
    const float* A = A0 + (size_t)b * sA;
    float* C = C0 + (size_t)b * sC;

    const int t = threadIdx.x;
    const int wid = t >> 5;
    const int m0 = (wid & 1) * 64, n0 = (wid >> 1) * 64;

    AccFrag acc[4][4];
#pragma unroll
    for (int i = 0; i < 4; i++)
#pragma unroll
        for (int j = 0; j < 4; j++) wmma::fill_fragment(acc[i][j], 0.0f);

    {
        char* buf = sm;
#pragma unroll
        for (int l = 0; l < 4; l++) {
            int e = t + l * 128;
            int r = e >> 2, kg = (e & 3) << 2;
            uint2 h, lo;
            split4(*(const float4*)&A[(size_t)(bi + r) * ND + kg], h, lo);
            *(uint2*)(buf + 0    + r * 48 + kg * 2) = h;
            *(uint2*)(buf + 6144 + r * 48 + kg * 2) = lo;
            split4(*(const float4*)&Bw[(size_t)(bj + r) * ND + kg], h, lo);
            *(uint2*)(buf + 12288 + r * 48 + kg * 2) = h;
            *(uint2*)(buf + 18432 + r * 48 + kg * 2) = lo;
        }
    }
    __syncthreads();

    const int T = ND / 16;
    for (int ti = 0; ti < T; ti++) {
        const int cur = ti & 1;
        float4 ra[4], rb[4];
        const bool more = (ti + 1 < T);
        if (more) {
            int k0 = (ti + 1) * 16;
#pragma unroll
            for (int l = 0; l < 4; l++) {
                int e = t + l * 128;
                int r = e >> 2, kg = (e & 3) << 2;
                ra[l] = *(const float4*)&A[(size_t)(bi + r) * ND + k0 + kg];
                rb[l] = *(const float4*)&Bw[(size_t)(bj + r) * ND + k0 + kg];
            }
        }
        {
            const __nv_bfloat16* Ah = (const __nv_bfloat16*)(sm + cur * ABT_BUF);
            const __nv_bfloat16* Al = (const __nv_bfloat16*)(sm + cur * ABT_BUF + 6144);
            const __nv_bfloat16* Bh = (const __nv_bfloat16*)(sm + cur * ABT_BUF + 12288);
            const __nv_bfloat16* Bl = (const __nv_bfloat16*)(sm + cur * ABT_BUF + 18432);
            wmma::fragment<wmma::matrix_a, 16, 16, 16, __nv_bfloat16, wmma::row_major> ah[4], al[4];
#pragma unroll
            for (int i = 0; i < 4; i++) {
                wmma::load_matrix_sync(ah[i], &Ah[(m0 + 16 * i) * KLD], KLD);
                wmma::load_matrix_sync(al[i], &Al[(m0 + 16 * i) * KLD], KLD);
            }
#pragma unroll
            for (int j = 0; j < 4; j++) {
                wmma::fragment<wmma::matrix_b, 16, 16, 16, __nv_bfloat16, wmma::col_major> bh, bl;
                wmma::load_matrix_sync(bh, &Bh[(n0 + 16 * j) * KLD], KLD);
                wmma::load_matrix_sync(bl, &Bl[(n0 + 16 * j) * KLD], KLD);
#pragma unroll
                for (int i = 0; i < 4; i++) {
                    wmma::mma_sync(acc[i][j], ah[i], bh, acc[i][j]);
                    wmma::mma_sync(acc[i][j], ah[i], bl, acc[i][j]);
                    wmma::mma_sync(acc[i][j], al[i], bh, acc[i][j]);
                }
            }
        }
        if (more) {
            char* buf = sm + (cur ^ 1) * ABT_BUF;
#pragma unroll
            for (int l = 0; l < 4; l++) {
                int e = t + l * 128;
                int r = e >> 2, kg = (e & 3) << 2;
                uint2 h, lo;
                split4(ra[l], h, lo);
                *(uint2*)(buf + 0    + r * 48 + kg * 2) = h;
                *(uint2*)(buf + 6144 + r * 48 + kg * 2) = lo;
                split4(rb[l], h, lo);
                *(uint2*)(buf + 12288 + r * 48 + kg * 2) = h;
                *(uint2*)(buf + 18432 + r * 48 + kg * 2) = lo;
            }
        }
        __syncthreads();
    }

#pragma unroll
    for (int i = 0; i < 4; i++)
#pragma unroll
        for (int j = 0; j < 4; j++)
            wmma::store_matrix_sync(&C[(size_t)(bi + m0 + 16 * i) * ND + bj + n0 + 16 * j],
                                    acc[i][j], ND, wmma::mem_row_major);
}

// ===========================================================================
// K5: Y_b = X_b * M_b — CTA tile 128x128, 4 warps (2x2), warp tile 64x64,
// kTile=16, double-buffered, bf16-split wmma, 2 CTAs/SM. (R14 committed)
// ===========================================================================
#define XM_BUF 20992
#define XM_SMEM (2 * XM_BUF)   // 41984

__global__ __launch_bounds__(128, 2) void k_xm(const float* __restrict__ X,
                                               float* __restrict__ Y) {
    extern __shared__ char sm[];
    const int b = blockIdx.z;
    const int bs = blockIdx.x * 128, bo = blockIdx.y * 128;
    const float* Xb = X + (size_t)b * NS * ND;
    const float* Mb = g_M + (size_t)b * ND * ND;
    float* Yb = Y + (size_t)b * NS * ND;

    const int t = threadIdx.x;
    const int wid = t >> 5;
    const int m0 = (wid & 1) * 64, n0 = (wid >> 1) * 64;

    AccFrag acc[4][4];
#pragma unroll
    for (int i = 0; i < 4; i++)
#pragma unroll
        for (int j = 0; j < 4; j++) wmma::fill_fragment(acc[i][j], 0.0f);

    {
        char* buf = sm;
#pragma unroll
        for (int l = 0; l < 4; l++) {
            int e = t + l * 128;
            int r = e >> 2, kg = (e & 3) << 2;
            uint2 h, lo;
            split4(*(const float4*)&Xb[(size_t)(bs + r) * ND + kg], h, lo);
            *(uint2*)(buf + 0    + r * 48 + kg * 2) = h;
            *(uint2*)(buf + 6144 + r * 48 + kg * 2) = lo;
            int row = e >> 5, col = (e & 31) << 2;
            split4(*(const float4*)&Mb[(size_t)row * ND + bo + col], h, lo);
            *(uint2*)(buf + 12288 + row * 272 + col * 2) = h;
            *(uint2*)(buf + 16640 + row * 272 + col * 2) = lo;
        }
    }
    __syncthreads();

    const int T = ND / 16;
    for (int ti = 0; ti < T; ti++) {
        const int cur = ti & 1;
        float4 ra[4], rb[4];
        const bool more = (ti + 1 < T);
        if (more) {
            int k0 = (ti + 1) * 16;
#pragma unroll
            for (int l = 0; l < 4; l++) {
                int e = t + l * 128;
                int r = e >> 2, kg = (e & 3) << 2;
                ra[l] = *(const float4*)&Xb[(size_t)(bs + r) * ND + k0 + kg];
                int row = e >> 5, col = (e & 31) << 2;
                rb[l] = *(const float4*)&Mb[(size_t)(k0 + row) * ND + bo + col];
            }
        }
        {
            const __nv_bfloat16* Ah = (const __nv_bfloat16*)(sm + cur * XM_BUF);
            const __nv_bfloat16* Al = (const __nv_bfloat16*)(sm + cur * XM_BUF + 6144);
            const __nv_bfloat16* Bh = (const __nv_bfloat16*)(sm + cur * XM_BUF + 12288);
            const __nv_bfloat16* Bl = (const __nv_bfloat16*)(sm + cur * XM_BUF + 16640);
            wmma::fragment<wmma::matrix_a, 16, 16, 16, __nv_bfloat16, wmma::row_major> ah[4], al[4];
#pragma unroll
            for (int i = 0; i < 4; i++) {
                wmma::load_matrix_sync(ah[i], &Ah[(m0 + 16 * i) * KLD], KLD);
                wmma::load_matrix_sync(al[i], &Al[(m0 + 16 * i) * KLD], KLD);
            }
#pragma unroll
            for (int j = 0; j < 4; j++) {
                wmma::fragment<wmma::matrix_b, 16, 16, 16, __nv_bfloat16, wmma::row_major> bh, bl;
                wmma::load_matrix_sync(bh, &Bh[n0 + 16 * j], NLD);
                wmma::load_matrix_sync(bl, &Bl[n0 + 16 * j], NLD);
#pragma unroll
                for (int i = 0; i < 4; i++) {
                    wmma::mma_sync(acc[i][j], ah[i], bh, acc[i][j]);
                    wmma::mma_sync(acc[i][j], ah[i], bl, acc[i][j]);
                    wmma::mma_sync(acc[i][j], al[i], bh, acc[i][j]);
                }
            }
        }
        if (more) {
            char* buf = sm + (cur ^ 1) * XM_BUF;
#pragma unroll
            for (int l = 0; l < 4; l++) {
                int e = t + l * 128;
                int r = e >> 2, kg = (e & 3) << 2;
                uint2 h, lo;
                split4(ra[l], h, lo);
                *(uint2*)(buf + 0    + r * 48 + kg * 2) = h;
                *(uint2*)(buf + 6144 + r * 48 + kg * 2) = lo;
                int row = e >> 5, col = (e & 31) << 2;
                split4(rb[l], h, lo);
                *(uint2*)(buf + 12288 + row * 272 + col * 2) = h;
                *(uint2*)(buf + 16640 + row * 272 + col * 2) = lo;
            }
        }
        __syncthreads();
    }

#pragma unroll
    for (int i = 0; i < 4; i++)
#pragma unroll
        for (int j = 0; j < 4; j++)
            wmma::store_matrix_sync(&Yb[(size_t)(bs + m0 + 16 * i) * ND + bo + n0 + 16 * j],
                                    acc[i][j], ND, wmma::mem_row_major);
}

// ===========================================================================
// K1: G_b = X_b^T X_b — NOW 4 warps (2x2), warp tile 64x64, block 128,
// 2 CTAs/SM, kTile=16, double-buffered. Symmetric upper-tri block pairs.
// grid (36, 1, NB), block 128. Static smem 34816 B.
// ===========================================================================
__global__ __launch_bounds__(128, 2) void k_xtx(const float* __restrict__ X) {
    const int b = blockIdx.z;
    int p = blockIdx.x, pi = 0;
    while (p >= 8 - pi) { p -= 8 - pi; pi++; }
    const int bi = pi * 128, bj = (pi + p) * 128;
    const float* Xb = X + (size_t)b * NS * ND;

    __shared__ __nv_bfloat16 Ah[2][16][NLD], Al[2][16][NLD];
    __shared__ __nv_bfloat16 Bh[2][16][NLD], Bl[2][16][NLD];

    const int t = threadIdx.x;
    const int wid = t >> 5;
    const int m0 = (wid & 1) * 64, n0 = (wid >> 1) * 64;

    AccFrag acc[4][4];
#pragma unroll
    for (int i = 0; i < 4; i++)
#pragma unroll
        for (int j = 0; j < 4; j++) wmma::fill_fragment(acc[i][j], 0.0f);

    // preload tile 0 (each operand: 16 rows x 32 float4 = 512; 4/thread)
#pragma unroll
    for (int l = 0; l < 4; l++) {
        int e = t + l * 128;
        int row = e >> 5, col4 = e & 31;
        uint2 h, lo;
        split4(*(const float4*)&Xb[(size_t)row * ND + bi + col4 * 4], h, lo);
        *(uint2*)&Ah[0][row][col4 * 4] = h; *(uint2*)&Al[0][row][col4 * 4] = lo;
        split4(*(const float4*)&Xb[(size_t)row * ND + bj + col4 * 4], h, lo);
        *(uint2*)&Bh[0][row][col4 * 4] = h; *(uint2*)&Bl[0][row][col4 * 4] = lo;
    }
    __syncthreads();

    const int T = NS / 16;
    for (int ti = 0; ti < T; ti++) {
        const int cur = ti & 1;
        float4 ra[4], rb[4];
        const bool more = (ti + 1 < T);
        if (more) {
            int y0 = (ti + 1) * 16;
#pragma unroll
            for (int l = 0; l < 4; l++) {
                int e = t + l * 128;
                int row = e >> 5, col4 = e & 31;
                ra[l] = *(const float4*)&Xb[(size_t)(y0 + row) * ND + bi + col4 * 4];
                rb[l] = *(const float4*)&Xb[(size_t)(y0 + row) * ND + bj + col4 * 4];
            }
        }
        {
            wmma::fragment<wmma::matrix_a, 16, 16, 16, __nv_bfloat16, wmma::col_major> ah[4], al[4];
#pragma unroll
            for (int i = 0; i < 4; i++) {
                wmma::load_matrix_sync(ah[i], &Ah[cur][0][m0 + 16 * i], NLD);
                wmma::load_matrix_sync(al[i], &Al[cur][0][m0 + 16 * i], NLD);
            }
#pragma unroll
            for (int j = 0; j < 4; j++) {
                wmma::fragment<wmma::matrix_b, 16, 16, 16, __nv_bfloat16, wmma::row_major> bh, bl;
                wmma::load_matrix_sync(bh, &Bh[cur][0][n0 + 16 * j], NLD);
                wmma::load_matrix_sync(bl, &Bl[cur][0][n0 + 16 * j], NLD);
#pragma unroll
                for (int i = 0; i < 4; i++) {
                    wmma::mma_sync(acc[i][j], ah[i], bh, acc[i][j]);
                    wmma::mma_sync(acc[i][j], ah[i], bl, acc[i][j]);
                    wmma::mma_sync(acc[i][j], al[i], bh, acc[i][j]);
                }
            }
        }
        if (more) {
            int nxt = cur ^ 1;
#pragma unroll
            for (int l = 0; l < 4; l++) {
                int e = t + l * 128;
                int row = e >> 5, col4 = e & 31;
                uint2 h, lo;
                split4(ra[l], h, lo);
                *(uint2*)&Ah[nxt][row][col4 * 4] = h; *(uint2*)&Al[nxt][row][col4 * 4] = lo;
                split4(rb[l], h, lo);
                *(uint2*)&Bh[nxt][row][col4 * 4] = h; *(uint2*)&Bl[nxt][row][col4 * 4] = lo;
            }
        }
        __syncthreads();
    }

    float* Gb = g_G + (size_t)b * ND * ND;
#pragma unroll
    for (int i = 0; i < 4; i++)
#pragma unroll
        for (int j = 0; j < 4; j++) {
            int mg = bi + m0 + 16 * i, ng = bj + n0 + 16 * j;
            wmma::store_matrix_sync(&Gb[(size_t)mg * ND + ng], acc[i][j], ND, wmma::mem_row_major);
            if (bi != bj)
                wmma::store_matrix_sync(&Gb[(size_t)ng * ND + mg], acc[i][j], ND, wmma::mem_col_major);
        }
}

// ===========================================================================
// K3: per (head, batch): S = Wk_h U_h / 8 ; A = softmax_rows(S) ;
//     P_h = Wv_h^T A   (fp32 SIMT) — unchanged
// ===========================================================================
__global__ __launch_bounds__(256, 2) void k_head(const float* __restrict__ Wk,
                                                 const float* __restrict__ Wv) {
    const int h = blockIdx.x, b = blockIdx.y;
    const float* Ub = g_U + (size_t)b * ND * ND;
    float* Pb       = g_P + (size_t)b * ND * ND;

    __shared__ float Ks[64][64];
    __shared__ float Us[64][64];
    __shared__ float Ss[64][64];

    const int t = threadIdx.x;
    const int tk = t >> 4, tq = t & 15;

    float acc[4][4];
#pragma unroll
    for (int u = 0; u < 4; u++)
#pragma unroll
        for (int v = 0; v < 4; v++) acc[u][v] = 0.f;

    for (int i0 = 0; i0 < ND; i0 += 64) {
#pragma unroll
        for (int l = 0; l < 4; l++) {
            int e = t + l * 256;
            int k = e >> 4, ig = (e & 15) << 2;
            float4 v = *(const float4*)&Wk[(size_t)(h * 64 + k) * ND + i0 + ig];
            Ks[ig + 0][k] = v.x; Ks[ig + 1][k] = v.y;
            Ks[ig + 2][k] = v.z; Ks[ig + 3][k] = v.w;
            *(float4*)&Us[k][ig] =
                *(const float4*)&Ub[(size_t)(i0 + k) * ND + h * 64 + ig];
        }
        __syncthreads();
#pragma unroll
        for (int ii = 0; ii < 64; ii++) {
            float a[4], bb[4];
            *(float4*)a  = *(float4*)&Ks[ii][tk * 4];
            *(float4*)bb = *(float4*)&Us[ii][tq * 4];
#pragma unroll
            for (int u = 0; u < 4; u++)
#pragma unroll
                for (int v = 0; v < 4; v++) acc[u][v] += a[u] * bb[v];
        }
        __syncthreads();
    }
#pragma unroll
    for (int u = 0; u < 4; u++)
#pragma unroll
        for (int v = 0; v < 4; v++)
            Ss[tk * 4 + u][tq * 4 + v] = acc[u][v] * 0.125f;  // 1/sqrt(64)
    __syncthreads();

    if (t < 64) {
        float m = -1e30f;
#pragma unroll 4
        for (int q = 0; q < 64; q++) m = fmaxf(m, Ss[t][q]);
        float s = 0.f;
#pragma unroll 4
        for (int q = 0; q < 64; q++) { float e = __expf(Ss[t][q] - m); Ss[t][q] = e; s += e; }
        float inv = 1.0f / s;
#pragma unroll 4
        for (int q = 0; q < 64; q++) Ss[t][q] *= inv;
    }
    __syncthreads();

    for (int i0 = 0; i0 < ND; i0 += 64) {
#pragma unroll
        for (int l = 0; l < 4; l++) {
            int e = t + l * 256;
            int k = e >> 4, ig = (e & 15) << 2;
            *(float4*)&Ks[k][ig] =
                *(const float4*)&Wv[(size_t)(h * 64 + k) * ND + i0 + ig];
        }
        __syncthreads();
        float acc2[4][4];
#pragma unroll
        for (int u = 0; u < 4; u++)
#pragma unroll
            for (int v = 0; v < 4; v++) acc2[u][v] = 0.f;
#pragma unroll
        for (int k = 0; k < 64; k++) {
            float a[4], bb[4];
            *(float4*)a  = *(float4*)&Ks[k][tk * 4];
            *(float4*)bb = *(float4*)&Ss[k][tq * 4];
#pragma unroll
            for (int u = 0; u < 4; u++)
#pragma unroll
                for (int v = 0; v < 4; v++) acc2[u][v] += a[u] * bb[v];
        }
        __syncthreads();
#pragma unroll
        for (int u = 0; u < 4; u++)
#pragma unroll
            for (int v = 0; v < 4; v++)
                Pb[(size_t)(i0 + tk * 4 + u) * ND + h * 64 + tq * 4 + v] = acc2[u][v];
    }
}

// ---------------------------------------------------------------------------
extern "C" void kernel_launch(void* const* d_in, const int* in_sizes, int n_in,
                              void* d_out, int out_size) {
    const float* x  = (const float*)d_in[0];
    const float* Wq = (const float*)d_in[1];
    const float* Wk = (const float*)d_in[2];
    const float* Wv = (const float*)d_in[3];
    const float* Wo = (const float*)d_in[4];
    float* y = (float*)d_out;

    float* pG = nullptr; cudaGetSymbolAddress((void**)&pG, g_G);
    float* pU = nullptr; cudaGetSymbolAddress((void**)&pU, g_U);
    float* pP = nullptr; cudaGetSymbolAddress((void**)&pP, g_P);
    float* pM = nullptr; cudaGetSymbolAddress((void**)&pM, g_M);

    cudaFuncSetAttribute(k_abt, cudaFuncAttributeMaxDynamicSharedMemorySize, ABT_SMEM);
    cudaFuncSetAttribute(k_xm,  cudaFuncAttributeMaxDynamicSharedMemorySize, XM_SMEM);

    // 1) Gram matrices: G_b = X_b^T X_b (symmetric, 36 block pairs)
    k_xtx<<<dim3(36, 1, NB), 128>>>(x);
    // 2) U_b = G_b Wq^T
    k_abt<<<dim3(8, 8, NB), 128, ABT_SMEM>>>(pG, (size_t)ND * ND, Wq, pU, (size_t)ND * ND);
    // 3) per-head scores + softmax + P_h = Wv_h^T A_h
    k_head<<<dim3(NH, NB), 256>>>(Wk, Wv);
    // 4) M_b = P_b Wo^T
    k_abt<<<dim3(8, 8, NB), 128, ABT_SMEM>>>(pP, (size_t)ND * ND, Wo, pM, (size_t)ND * ND);
    // 5) Y_b = X_b M_b
    k_xm<<<dim3(32, 8, NB), 128, XM_SMEM>>>(x, y);
}